// round 9
// baseline (speedup 1.0000x reference)
#include <cuda_runtime.h>
#include <math.h>

// Problem constants
#define BB 4
#define TT 2048
#define DD 128
#define HH 8
#define NQK (HH*DD)          // 1024

// Scratch: Q,K,V in [b][h][t][d] layout; AO in [b][t][h*d] layout.
__device__ float g_Q[BB*HH*TT*DD];
__device__ float g_K[BB*HH*TT*DD];
__device__ float g_V[BB*HH*TT*DD];
__device__ float g_AO[BB*TT*NQK];

// ---------------------------------------------------------------------------
// Kernel 1: QKV projections. C[8192,1024] = x[8192,128] @ W[128,1024]
// grid (16, 128, 3), block 256, static smem 34816 B.
// Output scattered to [b][h][t][d]; V scaled by 128^-0.25.
// ---------------------------------------------------------------------------
extern "C" __global__ void __launch_bounds__(256)
qkv_kernel(const float* __restrict__ x,
           const float* __restrict__ Wq,
           const float* __restrict__ Wk,
           const float* __restrict__ Wv)
{
    __shared__ float sA[64*68];   // x tile: 64 rows x 64 k (padded stride 68)
    __shared__ float sB[64*68];   // W tile: 64 k x 64 n (padded stride 68)

    const int n0 = blockIdx.x * 64;     // col tile in [0,1024)
    const int m0 = blockIdx.y * 64;     // row tile in [0,8192)
    const int which = blockIdx.z;

    const float* W = (which == 0) ? Wq : (which == 1) ? Wk : Wv;
    float* out = (which == 0) ? g_Q : (which == 1) ? g_K : g_V;
    // 128^-0.25 = 2^(-7/4) = 0.2973017787506803  (was wrongly 2^(-3/4) before!)
    const float oscale = (which == 2) ? 0.2973017787506803f : 1.0f;

    const int tid = threadIdx.x;
    const int ty = tid >> 4, tx = tid & 15;

    float acc[4][4] = {};

    for (int kc = 0; kc < 128; kc += 64) {
        __syncthreads();
        for (int i = tid; i < 64*16; i += 256) {
            int r = i >> 4, c4 = (i & 15) * 4;
            *reinterpret_cast<float4*>(&sA[r*68 + c4]) =
                *reinterpret_cast<const float4*>(&x[(size_t)(m0 + r)*128 + kc + c4]);
            *reinterpret_cast<float4*>(&sB[r*68 + c4]) =
                *reinterpret_cast<const float4*>(&W[(size_t)(kc + r)*1024 + n0 + c4]);
        }
        __syncthreads();

#pragma unroll 8
        for (int kk = 0; kk < 64; ++kk) {
            float4 b4 = *reinterpret_cast<float4*>(&sB[kk*68 + tx*4]);
            float a0 = sA[(ty*4+0)*68 + kk];
            float a1 = sA[(ty*4+1)*68 + kk];
            float a2 = sA[(ty*4+2)*68 + kk];
            float a3 = sA[(ty*4+3)*68 + kk];
            acc[0][0] += a0*b4.x; acc[0][1] += a0*b4.y; acc[0][2] += a0*b4.z; acc[0][3] += a0*b4.w;
            acc[1][0] += a1*b4.x; acc[1][1] += a1*b4.y; acc[1][2] += a1*b4.z; acc[1][3] += a1*b4.w;
            acc[2][0] += a2*b4.x; acc[2][1] += a2*b4.y; acc[2][2] += a2*b4.z; acc[2][3] += a2*b4.w;
            acc[3][0] += a3*b4.x; acc[3][1] += a3*b4.y; acc[3][2] += a3*b4.z; acc[3][3] += a3*b4.w;
        }
    }

    // Scatter: row m -> (b,t), col n -> (h,d). Layout [b][h][t][d].
    const int ncol = n0 + tx*4;            // 4-aligned, stays within one head
    const int h = ncol >> 7;
    const int d = ncol & 127;
#pragma unroll
    for (int i = 0; i < 4; ++i) {
        int m = m0 + ty*4 + i;
        int b = m >> 11, t = m & 2047;
        float4 v = make_float4(acc[i][0]*oscale, acc[i][1]*oscale,
                               acc[i][2]*oscale, acc[i][3]*oscale);
        *reinterpret_cast<float4*>(&out[(((size_t)(b*HH + h))*TT + t)*DD + d]) = v;
    }
}

// ---------------------------------------------------------------------------
// Kernel 2: causal flash attention per (b,h). BM=BN=64, D=128, 256 threads.
// Static smem: 3 x 16384 B = 49152 B.
// ---------------------------------------------------------------------------
extern "C" __global__ void __launch_bounds__(256)
flash_kernel()
{
    __shared__ float sA[64*64];
    __shared__ float sB[64*64];
    __shared__ float sC[64*64];

    const int qt = blockIdx.x;
    const int bh = blockIdx.y;
    const int b = bh >> 3, h = bh & 7;

    const float* Q = g_Q + (size_t)bh * TT * DD;
    const float* K = g_K + (size_t)bh * TT * DD;
    const float* V = g_V + (size_t)bh * TT * DD;

    const int tid = threadIdx.x;
    const int ty = tid >> 4, tx = tid & 15;
    const int q0 = qt * 64;

    float mrow[4], lrow[4], acc[4][8];
#pragma unroll
    for (int i = 0; i < 4; ++i) {
        mrow[i] = -INFINITY; lrow[i] = 0.f;
#pragma unroll
        for (int j = 0; j < 8; ++j) acc[i][j] = 0.f;
    }
    const float sscale = 0.08838834764831845f; // 128^-0.5

    for (int kv0 = 0; kv0 <= q0; kv0 += 64) {
        float S[4][4] = {};

        // ---- S = Q @ K^T over two d-halves ----
        for (int dh = 0; dh < 2; ++dh) {
            __syncthreads();   // prior phase done reading sA/sB
            for (int i = tid; i < 64*16; i += 256) {
                int r = i >> 4, c4 = (i & 15) * 4;
                *reinterpret_cast<float4*>(&sA[r*64 + c4]) =
                    *reinterpret_cast<const float4*>(&Q[(size_t)(q0 + r)*DD + dh*64 + c4]);
                float4 kv = *reinterpret_cast<const float4*>(&K[(size_t)(kv0 + r)*DD + dh*64 + c4]);
                int sw = r ^ (c4 & 28);
                sB[(c4+0)*64 + sw] = kv.x;
                sB[(c4+1)*64 + sw] = kv.y;
                sB[(c4+2)*64 + sw] = kv.z;
                sB[(c4+3)*64 + sw] = kv.w;
            }
            __syncthreads();

#pragma unroll 8
            for (int kk = 0; kk < 64; ++kk) {
                float4 b4 = *reinterpret_cast<float4*>(&sB[kk*64 + ((tx*4) ^ (kk & 28))]);
                float a0 = sA[(ty*4+0)*64 + kk];
                float a1 = sA[(ty*4+1)*64 + kk];
                float a2 = sA[(ty*4+2)*64 + kk];
                float a3 = sA[(ty*4+3)*64 + kk];
                S[0][0] += a0*b4.x; S[0][1] += a0*b4.y; S[0][2] += a0*b4.z; S[0][3] += a0*b4.w;
                S[1][0] += a1*b4.x; S[1][1] += a1*b4.y; S[1][2] += a1*b4.z; S[1][3] += a1*b4.w;
                S[2][0] += a2*b4.x; S[2][1] += a2*b4.y; S[2][2] += a2*b4.z; S[2][3] += a2*b4.w;
                S[3][0] += a3*b4.x; S[3][1] += a3*b4.y; S[3][2] += a3*b4.z; S[3][3] += a3*b4.w;
            }
        }

        // ---- scale + causal mask (diagonal tile only) ----
        const bool diag = (kv0 == q0);
#pragma unroll
        for (int i = 0; i < 4; ++i) {
            int t = q0 + ty*4 + i;
#pragma unroll
            for (int j = 0; j < 4; ++j) {
                float v = S[i][j] * sscale;
                if (diag && (kv0 + tx*4 + j > t)) v = -INFINITY;
                S[i][j] = v;
            }
        }

        // ---- online softmax (row groups = 16 lanes sharing ty) ----
        float p[4][4];
#pragma unroll
        for (int i = 0; i < 4; ++i) {
            float rm = fmaxf(fmaxf(S[i][0], S[i][1]), fmaxf(S[i][2], S[i][3]));
#pragma unroll
            for (int off = 8; off >= 1; off >>= 1)
                rm = fmaxf(rm, __shfl_xor_sync(0xffffffffu, rm, off, 16));
            float mnew = fmaxf(mrow[i], rm);
            float corr = __expf(mrow[i] - mnew);
            float rs = 0.f;
#pragma unroll
            for (int j = 0; j < 4; ++j) {
                p[i][j] = __expf(S[i][j] - mnew);
                rs += p[i][j];
            }
#pragma unroll
            for (int off = 8; off >= 1; off >>= 1)
                rs += __shfl_xor_sync(0xffffffffu, rs, off, 16);
            lrow[i] = lrow[i]*corr + rs;
            mrow[i] = mnew;
#pragma unroll
            for (int j = 0; j < 8; ++j) acc[i][j] *= corr;
        }

        __syncthreads();   // all threads finished S-phase reads of sA/sB

        // ---- stage P into C, V halves into A/B ----
#pragma unroll
        for (int i = 0; i < 4; ++i)
            *reinterpret_cast<float4*>(&sC[(ty*4+i)*64 + tx*4]) =
                make_float4(p[i][0], p[i][1], p[i][2], p[i][3]);
        for (int i = tid; i < 64*16; i += 256) {
            int s = i >> 4, c4 = (i & 15) * 4;
            *reinterpret_cast<float4*>(&sA[s*64 + c4]) =
                *reinterpret_cast<const float4*>(&V[(size_t)(kv0 + s)*DD + c4]);
            *reinterpret_cast<float4*>(&sB[s*64 + c4]) =
                *reinterpret_cast<const float4*>(&V[(size_t)(kv0 + s)*DD + 64 + c4]);
        }
        __syncthreads();

        // ---- O += P @ V ----
#pragma unroll 4
        for (int s = 0; s < 64; ++s) {
            float4 v0 = *reinterpret_cast<float4*>(&sA[s*64 + tx*4]);
            float4 v1 = *reinterpret_cast<float4*>(&sB[s*64 + tx*4]);
            float a0 = sC[(ty*4+0)*64 + s];
            float a1 = sC[(ty*4+1)*64 + s];
            float a2 = sC[(ty*4+2)*64 + s];
            float a3 = sC[(ty*4+3)*64 + s];
            acc[0][0]+=a0*v0.x; acc[0][1]+=a0*v0.y; acc[0][2]+=a0*v0.z; acc[0][3]+=a0*v0.w;
            acc[0][4]+=a0*v1.x; acc[0][5]+=a0*v1.y; acc[0][6]+=a0*v1.z; acc[0][7]+=a0*v1.w;
            acc[1][0]+=a1*v0.x; acc[1][1]+=a1*v0.y; acc[1][2]+=a1*v0.z; acc[1][3]+=a1*v0.w;
            acc[1][4]+=a1*v1.x; acc[1][5]+=a1*v1.y; acc[1][6]+=a1*v1.z; acc[1][7]+=a1*v1.w;
            acc[2][0]+=a2*v0.x; acc[2][1]+=a2*v0.y; acc[2][2]+=a2*v0.z; acc[2][3]+=a2*v0.w;
            acc[2][4]+=a2*v1.x; acc[2][5]+=a2*v1.y; acc[2][6]+=a2*v1.z; acc[2][7]+=a2*v1.w;
            acc[3][0]+=a3*v0.x; acc[3][1]+=a3*v0.y; acc[3][2]+=a3*v0.z; acc[3][3]+=a3*v0.w;
            acc[3][4]+=a3*v1.x; acc[3][5]+=a3*v1.y; acc[3][6]+=a3*v1.z; acc[3][7]+=a3*v1.w;
        }
    }

    // Epilogue: normalize + write AO in [b][t][h*d] layout
#pragma unroll
    for (int i = 0; i < 4; ++i) {
        float inv = 1.0f / lrow[i];
        int t = q0 + ty*4 + i;
        float* dst = &g_AO[(((size_t)b*TT + t)*NQK) + h*DD];
        *reinterpret_cast<float4*>(&dst[tx*4]) =
            make_float4(acc[i][0]*inv, acc[i][1]*inv, acc[i][2]*inv, acc[i][3]*inv);
        *reinterpret_cast<float4*>(&dst[64 + tx*4]) =
            make_float4(acc[i][4]*inv, acc[i][5]*inv, acc[i][6]*inv, acc[i][7]*inv);
    }
}

// ---------------------------------------------------------------------------
// Kernel 3: output projection. out[8192,128] = AO[8192,1024] @ Wu[1024,128] + bu
// grid (2, 128), block 256, static smem 34816 B.
// ---------------------------------------------------------------------------
extern "C" __global__ void __launch_bounds__(256)
proj_kernel(const float* __restrict__ Wu,
            const float* __restrict__ bu,
            float* __restrict__ out)
{
    __shared__ float sA[64*68];
    __shared__ float sB[64*68];

    const int n0 = blockIdx.x * 64;     // [0,128)
    const int m0 = blockIdx.y * 64;     // [0,8192)
    const int tid = threadIdx.x;
    const int ty = tid >> 4, tx = tid & 15;

    float acc[4][4] = {};

    for (int kc = 0; kc < 1024; kc += 64) {
        __syncthreads();
        for (int i = tid; i < 64*16; i += 256) {
            int r = i >> 4, c4 = (i & 15) * 4;
            *reinterpret_cast<float4*>(&sA[r*68 + c4]) =
                *reinterpret_cast<const float4*>(&g_AO[(size_t)(m0 + r)*NQK + kc + c4]);
            *reinterpret_cast<float4*>(&sB[r*68 + c4]) =
                *reinterpret_cast<const float4*>(&Wu[(size_t)(kc + r)*DD + n0 + c4]);
        }
        __syncthreads();

#pragma unroll 8
        for (int kk = 0; kk < 64; ++kk) {
            float4 b4 = *reinterpret_cast<float4*>(&sB[kk*68 + tx*4]);
            float a0 = sA[(ty*4+0)*68 + kk];
            float a1 = sA[(ty*4+1)*68 + kk];
            float a2 = sA[(ty*4+2)*68 + kk];
            float a3 = sA[(ty*4+3)*68 + kk];
            acc[0][0] += a0*b4.x; acc[0][1] += a0*b4.y; acc[0][2] += a0*b4.z; acc[0][3] += a0*b4.w;
            acc[1][0] += a1*b4.x; acc[1][1] += a1*b4.y; acc[1][2] += a1*b4.z; acc[1][3] += a1*b4.w;
            acc[2][0] += a2*b4.x; acc[2][1] += a2*b4.y; acc[2][2] += a2*b4.z; acc[2][3] += a2*b4.w;
            acc[3][0] += a3*b4.x; acc[3][1] += a3*b4.y; acc[3][2] += a3*b4.z; acc[3][3] += a3*b4.w;
        }
    }

    float4 bias = *reinterpret_cast<const float4*>(&bu[n0 + tx*4]);
#pragma unroll
    for (int i = 0; i < 4; ++i) {
        int m = m0 + ty*4 + i;
        *reinterpret_cast<float4*>(&out[(size_t)m*DD + n0 + tx*4]) =
            make_float4(acc[i][0]+bias.x, acc[i][1]+bias.y,
                        acc[i][2]+bias.z, acc[i][3]+bias.w);
    }
}

// ---------------------------------------------------------------------------
extern "C" void kernel_launch(void* const* d_in, const int* in_sizes, int n_in,
                              void* d_out, int out_size)
{
    // Robust input identification: x has 1048576 elems, bu has 128, the four
    // weight matrices have 131072 each (taken in metadata order Wq,Wk,Wv,Wu).
    const float* x = 0; const float* bu = 0;
    const float* Ws[4] = {0,0,0,0};
    int nw = 0;
    for (int i = 0; i < n_in; ++i) {
        if (in_sizes[i] == 1048576)      x = (const float*)d_in[i];
        else if (in_sizes[i] == 128)     bu = (const float*)d_in[i];
        else if (in_sizes[i] == 131072 && nw < 4) Ws[nw++] = (const float*)d_in[i];
    }
    if (!x || !bu || nw != 4) {  // fallback: positional (metadata order)
        x = (const float*)d_in[0];
        Ws[0] = (const float*)d_in[1];
        Ws[1] = (const float*)d_in[2];
        Ws[2] = (const float*)d_in[3];
        Ws[3] = (const float*)d_in[4];
        bu = (const float*)d_in[5];
    }
    float* out = (float*)d_out;

    qkv_kernel<<<dim3(16, 128, 3), 256>>>(x, Ws[0], Ws[1], Ws[2]);
    flash_kernel<<<dim3(32, 32), 256>>>();
    proj_kernel<<<dim3(2, 128), 256>>>(Ws[3], bu, out);
}

// round 12
// speedup vs baseline: 2.1567x; 2.1567x over previous
#include <cuda_runtime.h>
#include <math.h>
#include <stdint.h>

// Problem constants
#define BB 4
#define TT 2048
#define DD 128
#define HH 8
#define NQK (HH*DD)          // 1024

// Scratch: Q,K,V in [b][h][t][d] layout; AO in [b][t][h*d] layout.
__device__ float g_Q[BB*HH*TT*DD];
__device__ float g_K[BB*HH*TT*DD];
__device__ float g_V[BB*HH*TT*DD];
__device__ float g_AO[BB*TT*NQK];

// ---------------------------------------------------------------------------
// tf32 helpers
// ---------------------------------------------------------------------------
__device__ __forceinline__ float f2tf(float f) {
    uint32_t u;
    asm("cvt.rna.tf32.f32 %0, %1;" : "=r"(u) : "f"(f));
    return __uint_as_float(u);
}
__device__ __forceinline__ void mma8(float* c, const uint32_t* a, uint32_t b0, uint32_t b1) {
    asm volatile(
        "mma.sync.aligned.m16n8k8.row.col.f32.tf32.tf32.f32 "
        "{%0,%1,%2,%3}, {%4,%5,%6,%7}, {%8,%9}, {%0,%1,%2,%3};\n"
        : "+f"(c[0]), "+f"(c[1]), "+f"(c[2]), "+f"(c[3])
        : "r"(a[0]), "r"(a[1]), "r"(a[2]), "r"(a[3]), "r"(b0), "r"(b1));
}

// ---------------------------------------------------------------------------
// Kernel 1: QKV projections. C[8192,1024] = x[8192,128] @ W[128,1024]
// grid (16, 128, 3), block 256, static smem 34816 B.
// Output scattered to [b][h][t][d]; V scaled by 128^-0.25.
// ---------------------------------------------------------------------------
extern "C" __global__ void __launch_bounds__(256)
qkv_kernel(const float* __restrict__ x,
           const float* __restrict__ Wq,
           const float* __restrict__ Wk,
           const float* __restrict__ Wv)
{
    __shared__ float sA[64*68];
    __shared__ float sB[64*68];

    const int n0 = blockIdx.x * 64;
    const int m0 = blockIdx.y * 64;
    const int which = blockIdx.z;

    const float* W = (which == 0) ? Wq : (which == 1) ? Wk : Wv;
    float* out = (which == 0) ? g_Q : (which == 1) ? g_K : g_V;
    const float oscale = (which == 2) ? 0.2973017787506803f : 1.0f;  // 128^-0.25

    const int tid = threadIdx.x;
    const int ty = tid >> 4, tx = tid & 15;

    float acc[4][4] = {};

    for (int kc = 0; kc < 128; kc += 64) {
        __syncthreads();
        for (int i = tid; i < 64*16; i += 256) {
            int r = i >> 4, c4 = (i & 15) * 4;
            *reinterpret_cast<float4*>(&sA[r*68 + c4]) =
                *reinterpret_cast<const float4*>(&x[(size_t)(m0 + r)*128 + kc + c4]);
            *reinterpret_cast<float4*>(&sB[r*68 + c4]) =
                *reinterpret_cast<const float4*>(&W[(size_t)(kc + r)*1024 + n0 + c4]);
        }
        __syncthreads();

#pragma unroll 8
        for (int kk = 0; kk < 64; ++kk) {
            float4 b4 = *reinterpret_cast<float4*>(&sB[kk*68 + tx*4]);
            float a0 = sA[(ty*4+0)*68 + kk];
            float a1 = sA[(ty*4+1)*68 + kk];
            float a2 = sA[(ty*4+2)*68 + kk];
            float a3 = sA[(ty*4+3)*68 + kk];
            acc[0][0] += a0*b4.x; acc[0][1] += a0*b4.y; acc[0][2] += a0*b4.z; acc[0][3] += a0*b4.w;
            acc[1][0] += a1*b4.x; acc[1][1] += a1*b4.y; acc[1][2] += a1*b4.z; acc[1][3] += a1*b4.w;
            acc[2][0] += a2*b4.x; acc[2][1] += a2*b4.y; acc[2][2] += a2*b4.z; acc[2][3] += a2*b4.w;
            acc[3][0] += a3*b4.x; acc[3][1] += a3*b4.y; acc[3][2] += a3*b4.z; acc[3][3] += a3*b4.w;
        }
    }

    const int ncol = n0 + tx*4;
    const int h = ncol >> 7;
    const int d = ncol & 127;
#pragma unroll
    for (int i = 0; i < 4; ++i) {
        int m = m0 + ty*4 + i;
        int b = m >> 11, t = m & 2047;
        float4 v = make_float4(acc[i][0]*oscale, acc[i][1]*oscale,
                               acc[i][2]*oscale, acc[i][3]*oscale);
        *reinterpret_cast<float4*>(&out[(((size_t)(b*HH + h))*TT + t)*DD + d]) = v;
    }
}

// ---------------------------------------------------------------------------
// Kernel 2: causal flash attention, tf32 tensor cores (mma.sync m16n8k8).
// BM=128, BN=64, D=128, 256 threads (8 warps x 16 rows each).
// Dynamic smem 171008 B (opt-in).
// ---------------------------------------------------------------------------
#define SQ_S 132   // sQ row stride (floats); a-frag banks: 4*gid+tig distinct
#define SK_S 132   // sK row-major [s][d]; b-frag banks: 4*gid+tig distinct
#define SV_S 136   // sV row-major [s][d]; b-frag banks: 8*tig+gid distinct
#define SP_S 68    // sP [m][s]; a-frag banks: 4*gid+tig distinct
#define SMEM_FLASH ((128*SQ_S + 64*SK_S + 64*SV_S + 128*SP_S) * 4)  // 171008

extern "C" __global__ void __launch_bounds__(256, 1)
flash_tc()
{
    extern __shared__ float sm[];
    float* sQ = sm;                    // 128 x SQ_S
    float* sK = sQ + 128*SQ_S;         // 64 x SK_S
    float* sV = sK + 64*SK_S;          // 64 x SV_S
    float* sP = sV + 64*SV_S;          // 128 x SP_S

    const int qt = (int)gridDim.x - 1 - (int)blockIdx.x;  // longest blocks first
    const int bh = blockIdx.y;
    const int b = bh >> 3, h = bh & 7;
    const float* Q = g_Q + (size_t)bh * TT * DD;
    const float* K = g_K + (size_t)bh * TT * DD;
    const float* V = g_V + (size_t)bh * TT * DD;

    const int tid = threadIdx.x;
    const int w = tid >> 5, lane = tid & 31;
    const int gid = lane >> 2, tig = lane & 3;
    const int q0 = qt * 128;
    const float sscale = 0.08838834764831845f;  // 128^-0.5, folded into Q

    // Load Q tile (scaled + tf32-rounded)
    for (int i = tid; i < 128*32; i += 256) {
        int r = i >> 5, c4 = (i & 31) << 2;
        float4 q4 = *reinterpret_cast<const float4*>(&Q[(size_t)(q0 + r)*DD + c4]);
        float4 o = make_float4(f2tf(q4.x * sscale), f2tf(q4.y * sscale),
                               f2tf(q4.z * sscale), f2tf(q4.w * sscale));
        *reinterpret_cast<float4*>(&sQ[r*SQ_S + c4]) = o;
    }

    float OC[16][4];
#pragma unroll
    for (int nt = 0; nt < 16; ++nt)
#pragma unroll
        for (int j = 0; j < 4; ++j) OC[nt][j] = 0.f;
    float m0 = -INFINITY, m1 = -INFINITY, l0 = 0.f, l1 = 0.f;
    const int row0 = q0 + w*16 + gid;   // rows for c0/c1; c2/c3 are row0+8

    const int nkv = 2*qt + 2;
    for (int kvt = 0; kvt < nkv; ++kvt) {
        const int kv0 = kvt << 6;
        __syncthreads();   // previous iteration done reading sK/sV

        // Load K,V tiles (tf32-rounded), row-major
        for (int i = tid; i < 64*32; i += 256) {
            int s = i >> 5, c4 = (i & 31) << 2;
            float4 k4 = *reinterpret_cast<const float4*>(&K[(size_t)(kv0 + s)*DD + c4]);
            float4 v4 = *reinterpret_cast<const float4*>(&V[(size_t)(kv0 + s)*DD + c4]);
            float4 ko = make_float4(f2tf(k4.x), f2tf(k4.y), f2tf(k4.z), f2tf(k4.w));
            float4 vo = make_float4(f2tf(v4.x), f2tf(v4.y), f2tf(v4.z), f2tf(v4.w));
            *reinterpret_cast<float4*>(&sK[s*SK_S + c4]) = ko;
            *reinterpret_cast<float4*>(&sV[s*SV_S + c4]) = vo;
        }
        __syncthreads();

        // Warps whose 16 rows are all above this kv tile have nothing to do.
        if (kv0 <= q0 + w*16 + 15) {
            // ---- S = Q @ K^T : 16 rows x 64 cols per warp ----
            float SC[8][4];
#pragma unroll
            for (int nt = 0; nt < 8; ++nt)
#pragma unroll
                for (int j = 0; j < 4; ++j) SC[nt][j] = 0.f;

#pragma unroll 4
            for (int ks = 0; ks < 16; ++ks) {
                uint32_t A[4];
                const float* qb = &sQ[(w*16 + gid)*SQ_S + ks*8 + tig];
                A[0] = __float_as_uint(qb[0]);
                A[1] = __float_as_uint(qb[8*SQ_S]);
                A[2] = __float_as_uint(qb[4]);
                A[3] = __float_as_uint(qb[8*SQ_S + 4]);
#pragma unroll
                for (int nt = 0; nt < 8; ++nt) {
                    const float* kb = &sK[(nt*8 + gid)*SK_S + ks*8 + tig];
                    mma8(SC[nt], A, __float_as_uint(kb[0]), __float_as_uint(kb[4]));
                }
            }

            // ---- causal mask (only the last two kv tiles can clip) ----
            if (kvt >= 2*qt) {
#pragma unroll
                for (int nt = 0; nt < 8; ++nt) {
                    int c = kv0 + nt*8 + 2*tig;
                    if (c     > row0)     SC[nt][0] = -INFINITY;
                    if (c + 1 > row0)     SC[nt][1] = -INFINITY;
                    if (c     > row0 + 8) SC[nt][2] = -INFINITY;
                    if (c + 1 > row0 + 8) SC[nt][3] = -INFINITY;
                }
            }

            // ---- online softmax (row local to quad: shfl 1,2) ----
            float mx0 = -INFINITY, mx1 = -INFINITY;
#pragma unroll
            for (int nt = 0; nt < 8; ++nt) {
                mx0 = fmaxf(mx0, fmaxf(SC[nt][0], SC[nt][1]));
                mx1 = fmaxf(mx1, fmaxf(SC[nt][2], SC[nt][3]));
            }
            mx0 = fmaxf(mx0, __shfl_xor_sync(0xffffffffu, mx0, 1));
            mx0 = fmaxf(mx0, __shfl_xor_sync(0xffffffffu, mx0, 2));
            mx1 = fmaxf(mx1, __shfl_xor_sync(0xffffffffu, mx1, 1));
            mx1 = fmaxf(mx1, __shfl_xor_sync(0xffffffffu, mx1, 2));
            float mn0 = fmaxf(m0, mx0), mn1 = fmaxf(m1, mx1);
            float cr0 = __expf(m0 - mn0), cr1 = __expf(m1 - mn1);
            m0 = mn0; m1 = mn1;

            float s0 = 0.f, s1 = 0.f;
#pragma unroll
            for (int nt = 0; nt < 8; ++nt) {
                float p0 = __expf(SC[nt][0] - mn0);
                float p1 = __expf(SC[nt][1] - mn0);
                float p2 = __expf(SC[nt][2] - mn1);
                float p3 = __expf(SC[nt][3] - mn1);
                s0 += p0 + p1; s1 += p2 + p3;
                *reinterpret_cast<float2*>(&sP[(w*16 + gid)*SP_S + nt*8 + 2*tig]) =
                    make_float2(f2tf(p0), f2tf(p1));
                *reinterpret_cast<float2*>(&sP[(w*16 + gid + 8)*SP_S + nt*8 + 2*tig]) =
                    make_float2(f2tf(p2), f2tf(p3));
            }
            s0 += __shfl_xor_sync(0xffffffffu, s0, 1);
            s0 += __shfl_xor_sync(0xffffffffu, s0, 2);
            s1 += __shfl_xor_sync(0xffffffffu, s1, 1);
            s1 += __shfl_xor_sync(0xffffffffu, s1, 2);
            l0 = l0*cr0 + s0;
            l1 = l1*cr1 + s1;

#pragma unroll
            for (int nt = 0; nt < 16; ++nt) {
                OC[nt][0] *= cr0; OC[nt][1] *= cr0;
                OC[nt][2] *= cr1; OC[nt][3] *= cr1;
            }
            __syncwarp();   // sP rows are warp-private: warp-level ordering suffices

            // ---- O += P @ V : 16 rows x 128 cols per warp ----
#pragma unroll 4
            for (int ks = 0; ks < 8; ++ks) {
                uint32_t A[4];
                const float* pb = &sP[(w*16 + gid)*SP_S + ks*8 + tig];
                A[0] = __float_as_uint(pb[0]);
                A[1] = __float_as_uint(pb[8*SP_S]);
                A[2] = __float_as_uint(pb[4]);
                A[3] = __float_as_uint(pb[8*SP_S + 4]);
#pragma unroll
                for (int nt = 0; nt < 16; ++nt) {
                    const float* vb = &sV[(ks*8 + tig)*SV_S + nt*8 + gid];
                    mma8(OC[nt], A, __float_as_uint(vb[0]), __float_as_uint(vb[4*SV_S]));
                }
            }
        }
    }

    // Epilogue: normalize + write AO [b][t][h*d]
    float inv0 = 1.f / l0, inv1 = 1.f / l1;
    float* d0 = &g_AO[((size_t)b*TT + row0)*NQK + h*DD];
    float* d1 = &g_AO[((size_t)b*TT + row0 + 8)*NQK + h*DD];
#pragma unroll
    for (int nt = 0; nt < 16; ++nt) {
        int c = nt*8 + 2*tig;
        *reinterpret_cast<float2*>(&d0[c]) = make_float2(OC[nt][0]*inv0, OC[nt][1]*inv0);
        *reinterpret_cast<float2*>(&d1[c]) = make_float2(OC[nt][2]*inv1, OC[nt][3]*inv1);
    }
}

// ---------------------------------------------------------------------------
// Kernel 3: output projection. out[8192,128] = AO[8192,1024] @ Wu[1024,128] + bu
// grid (2, 128), block 256, static smem 34816 B.
// ---------------------------------------------------------------------------
extern "C" __global__ void __launch_bounds__(256)
proj_kernel(const float* __restrict__ Wu,
            const float* __restrict__ bu,
            float* __restrict__ out)
{
    __shared__ float sA[64*68];
    __shared__ float sB[64*68];

    const int n0 = blockIdx.x * 64;
    const int m0 = blockIdx.y * 64;
    const int tid = threadIdx.x;
    const int ty = tid >> 4, tx = tid & 15;

    float acc[4][4] = {};

    for (int kc = 0; kc < 1024; kc += 64) {
        __syncthreads();
        for (int i = tid; i < 64*16; i += 256) {
            int r = i >> 4, c4 = (i & 15) * 4;
            *reinterpret_cast<float4*>(&sA[r*68 + c4]) =
                *reinterpret_cast<const float4*>(&g_AO[(size_t)(m0 + r)*NQK + kc + c4]);
            *reinterpret_cast<float4*>(&sB[r*68 + c4]) =
                *reinterpret_cast<const float4*>(&Wu[(size_t)(kc + r)*DD + n0 + c4]);
        }
        __syncthreads();

#pragma unroll 8
        for (int kk = 0; kk < 64; ++kk) {
            float4 b4 = *reinterpret_cast<float4*>(&sB[kk*68 + tx*4]);
            float a0 = sA[(ty*4+0)*68 + kk];
            float a1 = sA[(ty*4+1)*68 + kk];
            float a2 = sA[(ty*4+2)*68 + kk];
            float a3 = sA[(ty*4+3)*68 + kk];
            acc[0][0] += a0*b4.x; acc[0][1] += a0*b4.y; acc[0][2] += a0*b4.z; acc[0][3] += a0*b4.w;
            acc[1][0] += a1*b4.x; acc[1][1] += a1*b4.y; acc[1][2] += a1*b4.z; acc[1][3] += a1*b4.w;
            acc[2][0] += a2*b4.x; acc[2][1] += a2*b4.y; acc[2][2] += a2*b4.z; acc[2][3] += a2*b4.w;
            acc[3][0] += a3*b4.x; acc[3][1] += a3*b4.y; acc[3][2] += a3*b4.z; acc[3][3] += a3*b4.w;
        }
    }

    float4 bias = *reinterpret_cast<const float4*>(&bu[n0 + tx*4]);
#pragma unroll
    for (int i = 0; i < 4; ++i) {
        int m = m0 + ty*4 + i;
        *reinterpret_cast<float4*>(&out[(size_t)m*DD + n0 + tx*4]) =
            make_float4(acc[i][0]+bias.x, acc[i][1]+bias.y,
                        acc[i][2]+bias.z, acc[i][3]+bias.w);
    }
}

// ---------------------------------------------------------------------------
extern "C" void kernel_launch(void* const* d_in, const int* in_sizes, int n_in,
                              void* d_out, int out_size)
{
    const float* x = 0; const float* bu = 0;
    const float* Ws[4] = {0,0,0,0};
    int nw = 0;
    for (int i = 0; i < n_in; ++i) {
        if (in_sizes[i] == 1048576)      x = (const float*)d_in[i];
        else if (in_sizes[i] == 128)     bu = (const float*)d_in[i];
        else if (in_sizes[i] == 131072 && nw < 4) Ws[nw++] = (const float*)d_in[i];
    }
    if (!x || !bu || nw != 4) {
        x = (const float*)d_in[0];
        Ws[0] = (const float*)d_in[1];
        Ws[1] = (const float*)d_in[2];
        Ws[2] = (const float*)d_in[3];
        Ws[3] = (const float*)d_in[4];
        bu = (const float*)d_in[5];
    }
    float* out = (float*)d_out;

    static int smem_set = 0;
    if (!smem_set) {
        cudaFuncSetAttribute(flash_tc, cudaFuncAttributeMaxDynamicSharedMemorySize,
                             SMEM_FLASH);
        smem_set = 1;
    }

    qkv_kernel<<<dim3(16, 128, 3), 256>>>(x, Ws[0], Ws[1], Ws[2]);
    flash_tc<<<dim3(16, 32), 256, SMEM_FLASH>>>();
    proj_kernel<<<dim3(2, 128), 256>>>(Ws[3], bu, out);
}

// round 13
// speedup vs baseline: 2.3831x; 1.1050x over previous
#include <cuda_runtime.h>
#include <math.h>
#include <stdint.h>

// Problem constants
#define BB 4
#define TT 2048
#define DD 128
#define HH 8
#define NQK (HH*DD)          // 1024

// Scratch: Q,K,V in [b][h][t][d] layout; AO in [b][t][h*d] layout.
__device__ float g_Q[BB*HH*TT*DD];
__device__ float g_K[BB*HH*TT*DD];
__device__ float g_V[BB*HH*TT*DD];
__device__ float g_AO[BB*TT*NQK];

// ---------------------------------------------------------------------------
// tf32 helpers
// ---------------------------------------------------------------------------
__device__ __forceinline__ float f2tf(float f) {
    uint32_t u;
    asm("cvt.rna.tf32.f32 %0, %1;" : "=r"(u) : "f"(f));
    return __uint_as_float(u);
}
__device__ __forceinline__ void mma8(float* c, const uint32_t* a, uint32_t b0, uint32_t b1) {
    asm volatile(
        "mma.sync.aligned.m16n8k8.row.col.f32.tf32.tf32.f32 "
        "{%0,%1,%2,%3}, {%4,%5,%6,%7}, {%8,%9}, {%0,%1,%2,%3};\n"
        : "+f"(c[0]), "+f"(c[1]), "+f"(c[2]), "+f"(c[3])
        : "r"(a[0]), "r"(a[1]), "r"(a[2]), "r"(a[3]), "r"(b0), "r"(b1));
}

// ---------------------------------------------------------------------------
// Kernel 1: QKV projections on tf32 tensor cores.
// C[8192,1024] = x[8192,128] @ W[128,1024]; BM=128, BN=64, K=128 one-shot.
// grid (16, 64, 3), block 256 (8 warps x m16), dyn smem 101376 B.
// Output scattered to [b][h][t][d]; V scaled by 128^-0.25.
// ---------------------------------------------------------------------------
#define GA_S 132
#define GW_S 132
#define SMEM_GTC ((128*GA_S + 64*GW_S) * 4)   // 101376

extern "C" __global__ void __launch_bounds__(256)
qkv_tc(const float* __restrict__ x,
       const float* __restrict__ Wq,
       const float* __restrict__ Wk,
       const float* __restrict__ Wv)
{
    extern __shared__ float sm[];
    float* sA = sm;                 // 128 x GA_S  (x rows, tf32)
    float* sW = sm + 128*GA_S;      // 64 x GW_S   (W^T: sW[n][k], tf32)

    const int n0 = blockIdx.x * 64;     // [0,1024)
    const int m0 = blockIdx.y * 128;    // [0,8192)
    const int which = blockIdx.z;

    const float* W = (which == 0) ? Wq : (which == 1) ? Wk : Wv;
    float* out = (which == 0) ? g_Q : (which == 1) ? g_K : g_V;
    const float oscale = (which == 2) ? 0.2973017787506803f : 1.0f;  // 128^-0.25

    const int tid = threadIdx.x;
    const int w = tid >> 5, lane = tid & 31;
    const int gid = lane >> 2, tig = lane & 3;

    // Load x tile [128][128] -> tf32
    for (int i = tid; i < 128*32; i += 256) {
        int r = i >> 5, c4 = (i & 31) << 2;
        float4 a4 = *reinterpret_cast<const float4*>(&x[(size_t)(m0 + r)*128 + c4]);
        *reinterpret_cast<float4*>(&sA[r*GA_S + c4]) =
            make_float4(f2tf(a4.x), f2tf(a4.y), f2tf(a4.z), f2tf(a4.w));
    }
    // Load W tile rows k=0..127, cols n0..n0+63, transposed into sW[n][k]
    for (int i = tid; i < 128*16; i += 256) {
        int k = i >> 4, c4 = (i & 15) << 2;
        float4 w4 = *reinterpret_cast<const float4*>(&W[(size_t)k*1024 + n0 + c4]);
        sW[(c4+0)*GW_S + k] = f2tf(w4.x);
        sW[(c4+1)*GW_S + k] = f2tf(w4.y);
        sW[(c4+2)*GW_S + k] = f2tf(w4.z);
        sW[(c4+3)*GW_S + k] = f2tf(w4.w);
    }
    __syncthreads();

    float SC[8][4];
#pragma unroll
    for (int nt = 0; nt < 8; ++nt)
#pragma unroll
        for (int j = 0; j < 4; ++j) SC[nt][j] = 0.f;

#pragma unroll 4
    for (int ks = 0; ks < 16; ++ks) {
        uint32_t A[4];
        const float* ab = &sA[(w*16 + gid)*GA_S + ks*8 + tig];
        A[0] = __float_as_uint(ab[0]);
        A[1] = __float_as_uint(ab[8*GA_S]);
        A[2] = __float_as_uint(ab[4]);
        A[3] = __float_as_uint(ab[8*GA_S + 4]);
#pragma unroll
        for (int nt = 0; nt < 8; ++nt) {
            const float* wb = &sW[(nt*8 + gid)*GW_S + ks*8 + tig];
            mma8(SC[nt], A, __float_as_uint(wb[0]), __float_as_uint(wb[4]));
        }
    }

    // Scatter: rows m0+w*16+gid (+8); cols n0+nt*8+2*tig (+1). One head per tile.
    const int h = n0 >> 7;
    const int dbase = n0 & 127;
#pragma unroll
    for (int half = 0; half < 2; ++half) {
        int m = m0 + w*16 + gid + half*8;
        int b = m >> 11, t = m & 2047;
        float* dst = &out[(((size_t)(b*HH + h))*TT + t)*DD + dbase];
#pragma unroll
        for (int nt = 0; nt < 8; ++nt) {
            *reinterpret_cast<float2*>(&dst[nt*8 + 2*tig]) =
                make_float2(SC[nt][2*half]*oscale, SC[nt][2*half+1]*oscale);
        }
    }
}

// ---------------------------------------------------------------------------
// Kernel 2: causal flash attention, tf32 tensor cores (mma.sync m16n8k8).
// BM=128, BN=64, D=128, 256 threads (8 warps x 16 rows each).
// Dynamic smem 171008 B (opt-in).  [UNCHANGED from R12 — passing @ ~440us]
// ---------------------------------------------------------------------------
#define SQ_S 132
#define SK_S 132
#define SV_S 136
#define SP_S 68
#define SMEM_FLASH ((128*SQ_S + 64*SK_S + 64*SV_S + 128*SP_S) * 4)  // 171008

extern "C" __global__ void __launch_bounds__(256, 1)
flash_tc()
{
    extern __shared__ float sm[];
    float* sQ = sm;                    // 128 x SQ_S
    float* sK = sQ + 128*SQ_S;         // 64 x SK_S
    float* sV = sK + 64*SK_S;          // 64 x SV_S
    float* sP = sV + 64*SV_S;          // 128 x SP_S

    const int qt = (int)gridDim.x - 1 - (int)blockIdx.x;  // longest blocks first
    const int bh = blockIdx.y;
    const int b = bh >> 3, h = bh & 7;
    const float* Q = g_Q + (size_t)bh * TT * DD;
    const float* K = g_K + (size_t)bh * TT * DD;
    const float* V = g_V + (size_t)bh * TT * DD;

    const int tid = threadIdx.x;
    const int w = tid >> 5, lane = tid & 31;
    const int gid = lane >> 2, tig = lane & 3;
    const int q0 = qt * 128;
    const float sscale = 0.08838834764831845f;  // 128^-0.5, folded into Q

    for (int i = tid; i < 128*32; i += 256) {
        int r = i >> 5, c4 = (i & 31) << 2;
        float4 q4 = *reinterpret_cast<const float4*>(&Q[(size_t)(q0 + r)*DD + c4]);
        float4 o = make_float4(f2tf(q4.x * sscale), f2tf(q4.y * sscale),
                               f2tf(q4.z * sscale), f2tf(q4.w * sscale));
        *reinterpret_cast<float4*>(&sQ[r*SQ_S + c4]) = o;
    }

    float OC[16][4];
#pragma unroll
    for (int nt = 0; nt < 16; ++nt)
#pragma unroll
        for (int j = 0; j < 4; ++j) OC[nt][j] = 0.f;
    float m0 = -INFINITY, m1 = -INFINITY, l0 = 0.f, l1 = 0.f;
    const int row0 = q0 + w*16 + gid;

    const int nkv = 2*qt + 2;
    for (int kvt = 0; kvt < nkv; ++kvt) {
        const int kv0 = kvt << 6;
        __syncthreads();

        for (int i = tid; i < 64*32; i += 256) {
            int s = i >> 5, c4 = (i & 31) << 2;
            float4 k4 = *reinterpret_cast<const float4*>(&K[(size_t)(kv0 + s)*DD + c4]);
            float4 v4 = *reinterpret_cast<const float4*>(&V[(size_t)(kv0 + s)*DD + c4]);
            float4 ko = make_float4(f2tf(k4.x), f2tf(k4.y), f2tf(k4.z), f2tf(k4.w));
            float4 vo = make_float4(f2tf(v4.x), f2tf(v4.y), f2tf(v4.z), f2tf(v4.w));
            *reinterpret_cast<float4*>(&sK[s*SK_S + c4]) = ko;
            *reinterpret_cast<float4*>(&sV[s*SV_S + c4]) = vo;
        }
        __syncthreads();

        if (kv0 <= q0 + w*16 + 15) {
            float SC[8][4];
#pragma unroll
            for (int nt = 0; nt < 8; ++nt)
#pragma unroll
                for (int j = 0; j < 4; ++j) SC[nt][j] = 0.f;

#pragma unroll 4
            for (int ks = 0; ks < 16; ++ks) {
                uint32_t A[4];
                const float* qb = &sQ[(w*16 + gid)*SQ_S + ks*8 + tig];
                A[0] = __float_as_uint(qb[0]);
                A[1] = __float_as_uint(qb[8*SQ_S]);
                A[2] = __float_as_uint(qb[4]);
                A[3] = __float_as_uint(qb[8*SQ_S + 4]);
#pragma unroll
                for (int nt = 0; nt < 8; ++nt) {
                    const float* kb = &sK[(nt*8 + gid)*SK_S + ks*8 + tig];
                    mma8(SC[nt], A, __float_as_uint(kb[0]), __float_as_uint(kb[4]));
                }
            }

            if (kvt >= 2*qt) {
#pragma unroll
                for (int nt = 0; nt < 8; ++nt) {
                    int c = kv0 + nt*8 + 2*tig;
                    if (c     > row0)     SC[nt][0] = -INFINITY;
                    if (c + 1 > row0)     SC[nt][1] = -INFINITY;
                    if (c     > row0 + 8) SC[nt][2] = -INFINITY;
                    if (c + 1 > row0 + 8) SC[nt][3] = -INFINITY;
                }
            }

            float mx0 = -INFINITY, mx1 = -INFINITY;
#pragma unroll
            for (int nt = 0; nt < 8; ++nt) {
                mx0 = fmaxf(mx0, fmaxf(SC[nt][0], SC[nt][1]));
                mx1 = fmaxf(mx1, fmaxf(SC[nt][2], SC[nt][3]));
            }
            mx0 = fmaxf(mx0, __shfl_xor_sync(0xffffffffu, mx0, 1));
            mx0 = fmaxf(mx0, __shfl_xor_sync(0xffffffffu, mx0, 2));
            mx1 = fmaxf(mx1, __shfl_xor_sync(0xffffffffu, mx1, 1));
            mx1 = fmaxf(mx1, __shfl_xor_sync(0xffffffffu, mx1, 2));
            float mn0 = fmaxf(m0, mx0), mn1 = fmaxf(m1, mx1);
            float cr0 = __expf(m0 - mn0), cr1 = __expf(m1 - mn1);
            m0 = mn0; m1 = mn1;

            float s0 = 0.f, s1 = 0.f;
#pragma unroll
            for (int nt = 0; nt < 8; ++nt) {
                float p0 = __expf(SC[nt][0] - mn0);
                float p1 = __expf(SC[nt][1] - mn0);
                float p2 = __expf(SC[nt][2] - mn1);
                float p3 = __expf(SC[nt][3] - mn1);
                s0 += p0 + p1; s1 += p2 + p3;
                *reinterpret_cast<float2*>(&sP[(w*16 + gid)*SP_S + nt*8 + 2*tig]) =
                    make_float2(f2tf(p0), f2tf(p1));
                *reinterpret_cast<float2*>(&sP[(w*16 + gid + 8)*SP_S + nt*8 + 2*tig]) =
                    make_float2(f2tf(p2), f2tf(p3));
            }
            s0 += __shfl_xor_sync(0xffffffffu, s0, 1);
            s0 += __shfl_xor_sync(0xffffffffu, s0, 2);
            s1 += __shfl_xor_sync(0xffffffffu, s1, 1);
            s1 += __shfl_xor_sync(0xffffffffu, s1, 2);
            l0 = l0*cr0 + s0;
            l1 = l1*cr1 + s1;

#pragma unroll
            for (int nt = 0; nt < 16; ++nt) {
                OC[nt][0] *= cr0; OC[nt][1] *= cr0;
                OC[nt][2] *= cr1; OC[nt][3] *= cr1;
            }
            __syncwarp();

#pragma unroll 4
            for (int ks = 0; ks < 8; ++ks) {
                uint32_t A[4];
                const float* pb = &sP[(w*16 + gid)*SP_S + ks*8 + tig];
                A[0] = __float_as_uint(pb[0]);
                A[1] = __float_as_uint(pb[8*SP_S]);
                A[2] = __float_as_uint(pb[4]);
                A[3] = __float_as_uint(pb[8*SP_S + 4]);
#pragma unroll
                for (int nt = 0; nt < 16; ++nt) {
                    const float* vb = &sV[(ks*8 + tig)*SV_S + nt*8 + gid];
                    mma8(OC[nt], A, __float_as_uint(vb[0]), __float_as_uint(vb[4*SV_S]));
                }
            }
        }
    }

    float inv0 = 1.f / l0, inv1 = 1.f / l1;
    float* d0 = &g_AO[((size_t)b*TT + row0)*NQK + h*DD];
    float* d1 = &g_AO[((size_t)b*TT + row0 + 8)*NQK + h*DD];
#pragma unroll
    for (int nt = 0; nt < 16; ++nt) {
        int c = nt*8 + 2*tig;
        *reinterpret_cast<float2*>(&d0[c]) = make_float2(OC[nt][0]*inv0, OC[nt][1]*inv0);
        *reinterpret_cast<float2*>(&d1[c]) = make_float2(OC[nt][2]*inv1, OC[nt][3]*inv1);
    }
}

// ---------------------------------------------------------------------------
// Kernel 3: output projection on tf32 tensor cores.
// out[8192,128] = AO[8192,1024] @ Wu[1024,128] + bu; BM=128, BN=64, K chunks of 128.
// grid (2, 64), block 256, dyn smem 101376 B.
// ---------------------------------------------------------------------------
extern "C" __global__ void __launch_bounds__(256)
proj_tc(const float* __restrict__ Wu,
        const float* __restrict__ bu,
        float* __restrict__ out)
{
    extern __shared__ float sm[];
    float* sA = sm;                 // 128 x GA_S
    float* sW = sm + 128*GA_S;      // 64 x GW_S  (Wu^T chunk: sW[n][k])

    const int n0 = blockIdx.x * 64;     // [0,128)
    const int m0 = blockIdx.y * 128;    // [0,8192)
    const int tid = threadIdx.x;
    const int w = tid >> 5, lane = tid & 31;
    const int gid = lane >> 2, tig = lane & 3;

    float SC[8][4];
#pragma unroll
    for (int nt = 0; nt < 8; ++nt)
#pragma unroll
        for (int j = 0; j < 4; ++j) SC[nt][j] = 0.f;

    for (int kc = 0; kc < 1024; kc += 128) {
        __syncthreads();
        for (int i = tid; i < 128*32; i += 256) {
            int r = i >> 5, c4 = (i & 31) << 2;
            float4 a4 = *reinterpret_cast<const float4*>(&g_AO[(size_t)(m0 + r)*NQK + kc + c4]);
            *reinterpret_cast<float4*>(&sA[r*GA_S + c4]) =
                make_float4(f2tf(a4.x), f2tf(a4.y), f2tf(a4.z), f2tf(a4.w));
        }
        for (int i = tid; i < 128*16; i += 256) {
            int k = i >> 4, c4 = (i & 15) << 2;
            float4 w4 = *reinterpret_cast<const float4*>(&Wu[(size_t)(kc + k)*DD + n0 + c4]);
            sW[(c4+0)*GW_S + k] = f2tf(w4.x);
            sW[(c4+1)*GW_S + k] = f2tf(w4.y);
            sW[(c4+2)*GW_S + k] = f2tf(w4.z);
            sW[(c4+3)*GW_S + k] = f2tf(w4.w);
        }
        __syncthreads();

#pragma unroll 4
        for (int ks = 0; ks < 16; ++ks) {
            uint32_t A[4];
            const float* ab = &sA[(w*16 + gid)*GA_S + ks*8 + tig];
            A[0] = __float_as_uint(ab[0]);
            A[1] = __float_as_uint(ab[8*GA_S]);
            A[2] = __float_as_uint(ab[4]);
            A[3] = __float_as_uint(ab[8*GA_S + 4]);
#pragma unroll
            for (int nt = 0; nt < 8; ++nt) {
                const float* wb = &sW[(nt*8 + gid)*GW_S + ks*8 + tig];
                mma8(SC[nt], A, __float_as_uint(wb[0]), __float_as_uint(wb[4]));
            }
        }
    }

#pragma unroll
    for (int half = 0; half < 2; ++half) {
        int m = m0 + w*16 + gid + half*8;
#pragma unroll
        for (int nt = 0; nt < 8; ++nt) {
            int c = n0 + nt*8 + 2*tig;
            *reinterpret_cast<float2*>(&out[(size_t)m*DD + c]) =
                make_float2(SC[nt][2*half] + bu[c], SC[nt][2*half+1] + bu[c+1]);
        }
    }
}

// ---------------------------------------------------------------------------
extern "C" void kernel_launch(void* const* d_in, const int* in_sizes, int n_in,
                              void* d_out, int out_size)
{
    const float* x = 0; const float* bu = 0;
    const float* Ws[4] = {0,0,0,0};
    int nw = 0;
    for (int i = 0; i < n_in; ++i) {
        if (in_sizes[i] == 1048576)      x = (const float*)d_in[i];
        else if (in_sizes[i] == 128)     bu = (const float*)d_in[i];
        else if (in_sizes[i] == 131072 && nw < 4) Ws[nw++] = (const float*)d_in[i];
    }
    if (!x || !bu || nw != 4) {
        x = (const float*)d_in[0];
        Ws[0] = (const float*)d_in[1];
        Ws[1] = (const float*)d_in[2];
        Ws[2] = (const float*)d_in[3];
        Ws[3] = (const float*)d_in[4];
        bu = (const float*)d_in[5];
    }
    float* out = (float*)d_out;

    static int smem_set = 0;
    if (!smem_set) {
        cudaFuncSetAttribute(flash_tc, cudaFuncAttributeMaxDynamicSharedMemorySize,
                             SMEM_FLASH);
        cudaFuncSetAttribute(qkv_tc,  cudaFuncAttributeMaxDynamicSharedMemorySize,
                             SMEM_GTC);
        cudaFuncSetAttribute(proj_tc, cudaFuncAttributeMaxDynamicSharedMemorySize,
                             SMEM_GTC);
        smem_set = 1;
    }

    qkv_tc<<<dim3(16, 64, 3), 256, SMEM_GTC>>>(x, Ws[0], Ws[1], Ws[2]);
    flash_tc<<<dim3(16, 32), 256, SMEM_FLASH>>>();
    proj_tc<<<dim3(2, 64), 256, SMEM_GTC>>>(Ws[3], bu, out);
}